// round 2
// baseline (speedup 1.0000x reference)
#include <cuda_runtime.h>

// CombinedLoraA: out[c, r] = sum_k x[xids[c*64+r], k] * A[wids[c], k, r]
//   x:    [512, 1, 4096] fp32
//   xids: [320*64] int32
//   wids: [320] int32
//   A:    [80, 4096, 64] fp32
//   out:  [320, 1, 64] fp32
//
// One CTA per c (grid 320). Per 128-wide k-tile:
//   - stage 64 gathered x rows into smem (float4, XOR swizzle -> conflict-free)
//   - thread (r = tid%64, kq = tid/64) accumulates 32 k's per tile:
//       A read direct from global, coalesced 128B (lanes over r)
//       x read from smem as LDS.128 (vector over k), swizzled conflict-free
//   - 4 kq-partials per r reduced through smem at the end.

constexpr int KDIM   = 4096;
constexpr int RANK   = 64;
constexpr int CDIM   = 320;
constexpr int KT     = 128;             // k-tile
constexpr int NTILES = KDIM / KT;       // 32
constexpr int NTHR   = 256;

__global__ __launch_bounds__(NTHR) void lora_a_kernel(
    const float* __restrict__ x,
    const int*   __restrict__ xids,
    const int*   __restrict__ wids,
    const float* __restrict__ A,
    float*       __restrict__ out)
{
    __shared__ float4 xs4[64 * 32];   // 64 rows x 32 float4 slots (swizzled), 32 KB
    __shared__ float  red[NTHR];      // kq-partials
    __shared__ int    toks[64];

    const int c   = blockIdx.x;
    const int tid = threadIdx.x;

    if (tid < 64) toks[tid] = xids[c * 64 + tid];
    const int w = wids[c];
    const float* __restrict__ Aw = A + (size_t)w * (KDIM * RANK);
    __syncthreads();

    // Each thread stages 8 float4 chunks per tile; its rows are fixed.
    const int srow0 = tid >> 5;       // 0..7
    const int sc4   = tid & 31;       // float4 column within row
    int trow[8];
#pragma unroll
    for (int i = 0; i < 8; ++i) trow[i] = toks[srow0 + i * 8];

    const int r   = tid & 63;         // output rank index
    const int kq  = tid >> 6;         // 0..3, k-quarter of the tile
    const int rsw = r & 31;           // swizzle key

    float acc = 0.0f;

    for (int t = 0; t < NTILES; ++t) {
        const int k0 = t * KT;

        // ---- stage x tile (coalesced global float4, swizzled smem) ----
#pragma unroll
        for (int i = 0; i < 8; ++i) {
            const int row = srow0 + i * 8;
            const float4 v = *reinterpret_cast<const float4*>(
                x + (size_t)trow[i] * KDIM + k0 + sc4 * 4);
            xs4[row * 32 + (sc4 ^ (row & 31))] = v;
        }
        __syncthreads();

        // ---- compute: 8 float4 k-groups = 32 k's for this (r, kq) ----
        const float* __restrict__ ap0 = Aw + (size_t)k0 * RANK + r;
#pragma unroll
        for (int g = 0; g < 8; ++g) {
            const int kk4 = kq * 8 + g;                    // float4 slot in tile
            const float4 xv = xs4[r * 32 + (kk4 ^ rsw)];
            const float* __restrict__ ap = ap0 + (size_t)kk4 * 4 * RANK;
            acc = fmaf(ap[0 * RANK], xv.x, acc);
            acc = fmaf(ap[1 * RANK], xv.y, acc);
            acc = fmaf(ap[2 * RANK], xv.z, acc);
            acc = fmaf(ap[3 * RANK], xv.w, acc);
        }
        __syncthreads();
    }

    // ---- reduce 4 kq partials per r ----
    red[tid] = acc;
    __syncthreads();
    if (tid < 64) {
        out[c * RANK + tid] =
            red[tid] + red[64 + tid] + red[128 + tid] + red[192 + tid];
    }
}

extern "C" void kernel_launch(void* const* d_in, const int* in_sizes, int n_in,
                              void* d_out, int out_size)
{
    const float* x    = (const float*)d_in[0];   // 512*1*4096 fp32
    const int*   xids = (const int*)  d_in[1];   // 20480 int32
    const int*   wids = (const int*)  d_in[2];   // 320 int32
    const float* A    = (const float*)d_in[3];   // 80*4096*64 fp32
    float*       out  = (float*)d_out;           // 320*1*64 fp32

    lora_a_kernel<<<CDIM, NTHR>>>(x, xids, wids, A, out);
}

// round 3
// speedup vs baseline: 2.5189x; 2.5189x over previous
#include <cuda_runtime.h>

// CombinedLoraA: out[c, r] = sum_k x[xids[c*64+r], k] * A[wids[c], k, r]
//   x:    [512, 1, 4096] fp32
//   xids: [320*64] int32
//   wids: [320] int32
//   A:    [80, 4096, 64] fp32
//   out:  [320, 1, 64] fp32
//
// R2: latency-bound fix. K-split x4 (grid 320x4 -> ~62% occ vs 26%),
// partials in device scratch + tiny reduce kernel. 4 rotating accumulators
// break the FMA RAW chain so A-loads overlap. Inner layout unchanged:
// A LDG coalesced over r; x staged to smem (XOR swizzle), LDS.128 over k.

constexpr int KDIM   = 4096;
constexpr int RANK   = 64;
constexpr int CDIM   = 320;
constexpr int KT     = 128;              // k-tile
constexpr int KSPLIT = 4;
constexpr int TILES_PER_SPLIT = KDIM / KT / KSPLIT;   // 8
constexpr int NTHR   = 256;

__device__ float g_partial[KSPLIT * CDIM * RANK];

__global__ __launch_bounds__(NTHR) void lora_a_partial(
    const float* __restrict__ x,
    const int*   __restrict__ xids,
    const int*   __restrict__ wids,
    const float* __restrict__ A)
{
    __shared__ float4 xs4[64 * 32];   // 64 rows x 32 float4 slots (swizzled), 32 KB
    __shared__ float  red[NTHR];
    __shared__ int    toks[64];

    const int c   = blockIdx.x;
    const int ks  = blockIdx.y;
    const int tid = threadIdx.x;

    if (tid < 64) toks[tid] = xids[c * 64 + tid];
    const int w = wids[c];
    const float* __restrict__ Aw = A + (size_t)w * (KDIM * RANK);
    __syncthreads();

    // staging assignment: fixed rows, fixed float4 column per thread
    const int srow0 = tid >> 5;       // 0..7
    const int sc4   = tid & 31;       // float4 column within row
    int trow[8];
#pragma unroll
    for (int i = 0; i < 8; ++i) trow[i] = toks[srow0 + i * 8];

    const int r   = tid & 63;         // output rank index
    const int kq  = tid >> 6;         // 0..3, k-quarter of the tile
    const int rsw = r & 31;           // swizzle key

    float acc0 = 0.0f, acc1 = 0.0f, acc2 = 0.0f, acc3 = 0.0f;

#pragma unroll 1
    for (int t = ks * TILES_PER_SPLIT; t < (ks + 1) * TILES_PER_SPLIT; ++t) {
        const int k0 = t * KT;

        // ---- stage x tile (coalesced global float4, swizzled smem) ----
#pragma unroll
        for (int i = 0; i < 8; ++i) {
            const int row = srow0 + i * 8;
            const float4 v = *reinterpret_cast<const float4*>(
                x + (size_t)trow[i] * KDIM + k0 + sc4 * 4);
            xs4[row * 32 + (sc4 ^ (row & 31))] = v;
        }
        __syncthreads();

        // ---- compute: 8 float4 k-groups = 32 k's for this (r, kq) ----
        const float* __restrict__ ap0 = Aw + (size_t)k0 * RANK + r;
#pragma unroll
        for (int g = 0; g < 8; g += 4) {
#pragma unroll
            for (int j = 0; j < 4; ++j) {
                const int kk4 = kq * 8 + g + j;            // float4 slot in tile
                const float4 xv = xs4[r * 32 + (kk4 ^ rsw)];
                const float* __restrict__ ap = ap0 + (size_t)kk4 * 4 * RANK;
                float pa = ap[0 * RANK], pb = ap[1 * RANK];
                float pc = ap[2 * RANK], pd = ap[3 * RANK];
                if (j == 0) { acc0 = fmaf(pa, xv.x, acc0); acc0 = fmaf(pb, xv.y, acc0);
                              acc0 = fmaf(pc, xv.z, acc0); acc0 = fmaf(pd, xv.w, acc0); }
                if (j == 1) { acc1 = fmaf(pa, xv.x, acc1); acc1 = fmaf(pb, xv.y, acc1);
                              acc1 = fmaf(pc, xv.z, acc1); acc1 = fmaf(pd, xv.w, acc1); }
                if (j == 2) { acc2 = fmaf(pa, xv.x, acc2); acc2 = fmaf(pb, xv.y, acc2);
                              acc2 = fmaf(pc, xv.z, acc2); acc2 = fmaf(pd, xv.w, acc2); }
                if (j == 3) { acc3 = fmaf(pa, xv.x, acc3); acc3 = fmaf(pb, xv.y, acc3);
                              acc3 = fmaf(pc, xv.z, acc3); acc3 = fmaf(pd, xv.w, acc3); }
            }
        }
        __syncthreads();
    }

    // ---- reduce 4 kq partials per r, write split partial ----
    red[tid] = (acc0 + acc1) + (acc2 + acc3);
    __syncthreads();
    if (tid < 64) {
        g_partial[(size_t)ks * (CDIM * RANK) + c * RANK + tid] =
            red[tid] + red[64 + tid] + red[128 + tid] + red[192 + tid];
    }
}

__global__ void lora_a_reduce(float* __restrict__ out)
{
    const int idx = blockIdx.x * blockDim.x + threadIdx.x;   // 0..20479
    if (idx < CDIM * RANK) {
        float s = g_partial[idx];
#pragma unroll
        for (int ks = 1; ks < KSPLIT; ++ks)
            s += g_partial[ks * (CDIM * RANK) + idx];
        out[idx] = s;
    }
}

extern "C" void kernel_launch(void* const* d_in, const int* in_sizes, int n_in,
                              void* d_out, int out_size)
{
    const float* x    = (const float*)d_in[0];   // 512*1*4096 fp32
    const int*   xids = (const int*)  d_in[1];   // 20480 int32
    const int*   wids = (const int*)  d_in[2];   // 320 int32
    const float* A    = (const float*)d_in[3];   // 80*4096*64 fp32
    float*       out  = (float*)d_out;           // 320*1*64 fp32

    dim3 grid(CDIM, KSPLIT);
    lora_a_partial<<<grid, NTHR>>>(x, xids, wids, A);
    lora_a_reduce<<<(CDIM * RANK + 255) / 256, 256>>>(out);
}

// round 4
// speedup vs baseline: 2.9193x; 1.1590x over previous
#include <cuda_runtime.h>

// CombinedLoraA: out[c, r] = sum_k x[xids[c*64+r], k] * A[wids[c], k, r]
//   x:[512,1,4096] f32  xids:[20480] i32  wids:[320] i32  A:[80,4096,64] f32
//   out:[320,1,64] f32
//
// R3: L2-traffic elimination. Per CTA: a 32-wide k-range of ALL 512 x rows
// lives in smem (64 KB, XOR-swizzled float4); A[w, krange, r] lives in 32
// registers per thread (lane = r, coalesced LDG, loaded once per adapter after
// grouping c's by wid). k-partials go to device scratch; reduce kernel sums.
// Traffic 640 MB -> ~170 MB; new bound = smem crossbar (~17 us model).

constexpr int KDIM   = 4096;
constexpr int RANK   = 64;
constexpr int CDIM   = 320;
constexpr int NADAPT = 80;
constexpr int NTOK   = 512;
constexpr int KR     = 32;               // k per range
constexpr int NKR    = KDIM / KR;        // 128
constexpr int ASPLIT = 7;                // adapter slots -> grid 128*7=896 CTAs
constexpr int NTHR   = 256;
constexpr int NPAIR  = CDIM * RANK;      // 20480

constexpr int SMEM_BYTES = NTOK * KR * 4 + CDIM * 4 + (NADAPT + 1) * 4; // 67140

__device__ float g_scratch[NKR * NPAIR];     // 10.5 MB k-partials
__device__ int   g_perm[CDIM];
__device__ int   g_seg[NADAPT + 1];

// ---- setup: counting-sort c's by wids[c] -> perm + segment starts ----
__global__ void setup_kernel(const int* __restrict__ wids)
{
    __shared__ int cnt[NADAPT], ofs[NADAPT];
    const int tid = threadIdx.x;
    if (tid < NADAPT) cnt[tid] = 0;
    __syncthreads();
    if (tid < CDIM) atomicAdd(&cnt[wids[tid]], 1);
    __syncthreads();
    if (tid == 0) {
        int run = 0;
        for (int w = 0; w < NADAPT; ++w) { g_seg[w] = run; ofs[w] = run; run += cnt[w]; }
        g_seg[NADAPT] = run;
    }
    __syncthreads();
    if (tid < CDIM) {
        int p = atomicAdd(&ofs[wids[tid]], 1);   // order within adapter irrelevant
        g_perm[p] = tid;
    }
}

// ---- main: one CTA = (k-range, adapter-slot) ----
__global__ __launch_bounds__(NTHR, 3) void lora_main(
    const float* __restrict__ x,
    const int*   __restrict__ xids,
    const float* __restrict__ A)
{
    extern __shared__ float smem[];
    float4* xs4    = reinterpret_cast<float4*>(smem);          // 512 rows x 8 f4 slots
    int*    perm_s = reinterpret_cast<int*>(smem + NTOK * KR); // +16384 floats
    int*    seg_s  = perm_s + CDIM;

    const int tid   = threadIdx.x;
    const int kr0   = blockIdx.x * KR;
    const int aslot = blockIdx.y;

    // stage x k-range for ALL 512 rows; slot = k4 ^ (row&7) (conflict-free STS,
    // compute-side spread over 8 float4 bank-groups keyed by token)
    for (int i = tid; i < NTOK * 8; i += NTHR) {
        const int row = i >> 3, k4 = i & 7;
        const float4 v = *reinterpret_cast<const float4*>(
            x + (size_t)row * KDIM + kr0 + k4 * 4);
        xs4[row * 8 + (k4 ^ (row & 7))] = v;
    }
    for (int i = tid; i < CDIM; i += NTHR)       perm_s[i] = g_perm[i];
    for (int i = tid; i < NADAPT + 1; i += NTHR) seg_s[i]  = g_seg[i];
    __syncthreads();

    const int r = tid & 63;          // lane-contiguous rank index
    const int g = tid >> 6;          // 4 independent thread-groups
    const int w_lo = (aslot * NADAPT) / ASPLIT;
    const int w_hi = ((aslot + 1) * NADAPT) / ASPLIT;

    float* __restrict__ scr = g_scratch + (size_t)blockIdx.x * NPAIR;

    for (int w = w_lo + g; w < w_hi; w += 4) {
        const int lo = seg_s[w], hi = seg_s[w + 1];
        if (lo >= hi) continue;

        // A[w, kr0..kr0+32, r] -> 32 registers (coalesced over r, 32 lines)
        float a[KR];
        const float* __restrict__ Ap = A + ((size_t)w * KDIM + kr0) * RANK + r;
#pragma unroll
        for (int j = 0; j < KR; ++j) a[j] = Ap[j * RANK];

        // software-pipelined token fetch
        int ci = lo;
        int c  = perm_s[ci];
        int t  = xids[c * 64 + r];
        while (ci < hi) {
            const int c_cur = c, t_cur = t;
            ++ci;
            if (ci < hi) { c = perm_s[ci]; t = xids[c * 64 + r]; }

            const int s = t_cur & 7;
            const float4* __restrict__ xrow = xs4 + t_cur * 8;
            float acc0 = 0.f, acc1 = 0.f, acc2 = 0.f, acc3 = 0.f;
#pragma unroll
            for (int k4 = 0; k4 < 8; ++k4) {
                const float4 xv = xrow[k4 ^ s];
                acc0 = fmaf(a[k4 * 4 + 0], xv.x, acc0);
                acc1 = fmaf(a[k4 * 4 + 1], xv.y, acc1);
                acc2 = fmaf(a[k4 * 4 + 2], xv.z, acc2);
                acc3 = fmaf(a[k4 * 4 + 3], xv.w, acc3);
            }
            scr[c_cur * 64 + r] = (acc0 + acc1) + (acc2 + acc3);
        }
    }
}

// ---- reduce: sum 128 k-partials per pair (4 rotating accumulators, MLP) ----
__global__ void reduce_kernel(float* __restrict__ out)
{
    const int p = blockIdx.x * blockDim.x + threadIdx.x;
    if (p >= NPAIR) return;
    float s0 = 0.f, s1 = 0.f, s2 = 0.f, s3 = 0.f;
#pragma unroll 8
    for (int kr = 0; kr < NKR; kr += 4) {
        s0 += g_scratch[(size_t)(kr + 0) * NPAIR + p];
        s1 += g_scratch[(size_t)(kr + 1) * NPAIR + p];
        s2 += g_scratch[(size_t)(kr + 2) * NPAIR + p];
        s3 += g_scratch[(size_t)(kr + 3) * NPAIR + p];
    }
    out[p] = (s0 + s1) + (s2 + s3);
}

extern "C" void kernel_launch(void* const* d_in, const int* in_sizes, int n_in,
                              void* d_out, int out_size)
{
    const float* x    = (const float*)d_in[0];
    const int*   xids = (const int*)  d_in[1];
    const int*   wids = (const int*)  d_in[2];
    const float* A    = (const float*)d_in[3];
    float*       out  = (float*)d_out;

    cudaFuncSetAttribute(lora_main,
                         cudaFuncAttributeMaxDynamicSharedMemorySize, SMEM_BYTES);

    setup_kernel<<<1, CDIM>>>(wids);
    lora_main<<<dim3(NKR, ASPLIT), NTHR, SMEM_BYTES>>>(x, xids, A);
    reduce_kernel<<<(NPAIR + 255) / 256, 256>>>(out);
}